// round 2
// baseline (speedup 1.0000x reference)
#include <cuda_runtime.h>
#include <math.h>

#define NN 50000
#define NE 500000
#define NG 2000

// ---------------- scratch (device globals) ----------------
__device__ float f_x1  [NN * 128];
__device__ float f_p   [NN * 128];      // p / xp
__device__ float f_h   [NN * 128];
__device__ float f_xcur[NN * 128];
__device__ float f_gi  [NN * 3 * 128];  // also reused as tsum (first NN*128)
__device__ float f_as  [NN];
__device__ float f_ad  [NN];
__device__ float g_agg [NG * 128];
__device__ float g_out [NG * 128];
__device__ float g_hh  [NG * 128];
__device__ float g_tmp [NG * 128];
__device__ float g_gi  [NG * 4 * 128];
__device__ float g_gh  [NG * 4 * 128];
// CSR
__device__ int c_cnt[NN];
__device__ int c_off[NN + 1];
__device__ int c_pos[NN];
__device__ int c_eid[NE];

__device__ __forceinline__ float sigm(float x) { return 1.0f / (1.0f + expf(-x)); }

// ---------------- CSR build ----------------
__global__ void zero_i_kernel(int* p, int n) {
    int t = blockIdx.x * blockDim.x + threadIdx.x;
    if (t < n) p[t] = 0;
}
__global__ void hist_kernel(const int* __restrict__ dst, int* __restrict__ cnt) {
    int e = blockIdx.x * blockDim.x + threadIdx.x;
    if (e < NE) atomicAdd(&cnt[dst[e]], 1);
}
__global__ void __launch_bounds__(1024) scan_kernel(const int* __restrict__ cnt,
                                                    int* __restrict__ off, int* __restrict__ pos) {
    __shared__ int sm[1024];
    __shared__ int s_carry;
    const int tid = threadIdx.x;
    if (tid == 0) s_carry = 0;
    __syncthreads();
    const int CH = 1024 * 8;
    for (int base = 0; base < NN; base += CH) {
        int v[8]; int s = 0;
        int i0 = base + tid * 8;
#pragma unroll
        for (int j = 0; j < 8; ++j) {
            int i = i0 + j;
            v[j] = (i < NN) ? cnt[i] : 0;
            s += v[j];
        }
        sm[tid] = s;
        __syncthreads();
        for (int d = 1; d < 1024; d <<= 1) {
            int t = (tid >= d) ? sm[tid - d] : 0;
            __syncthreads();
            sm[tid] += t;
            __syncthreads();
        }
        int pref = sm[tid] - s + s_carry;
        int total = sm[1023];
#pragma unroll
        for (int j = 0; j < 8; ++j) {
            int i = i0 + j;
            if (i < NN) { off[i] = pref; pos[i] = pref; }
            pref += v[j];
        }
        __syncthreads();
        if (tid == 0) s_carry += total;
        __syncthreads();
    }
    if (tid == 0) off[NN] = NE;
}
__global__ void fill_kernel(const int* __restrict__ dst, int* __restrict__ pos,
                            int* __restrict__ eid) {
    int e = blockIdx.x * blockDim.x + threadIdx.x;
    if (e < NE) {
        int idx = atomicAdd(&pos[dst[e]], 1);
        eid[idx] = e;
    }
}

// ---------------- dense GEMM ----------------
// out[n, jbase + tid + c*128] = act(sum_k A[n,k]*W[(j)*wstride+k] + b)
// EPI==1: GRU combine epilogue (JPT must be 3): gates from acc (gh side),
//         gi precomputed, hprev = A row; out = relu(gru) [NN x 128]
template <int K, int JPT, int ACT, int EPI>
__global__ void __launch_bounds__(128) dense_kernel(
    const float* __restrict__ A, const float* __restrict__ W,
    const float* __restrict__ bias, float* __restrict__ out,
    const float* __restrict__ gi, int n, int Jtotal, int wstride)
{
    constexpr int KP = K + 4;
    constexpr int NT = 16;
    constexpr int NPRE = NT * K / 512;
    extern __shared__ float sm[];
    float* Ws = sm;                     // JPT*128*KP
    float* ins = sm + JPT * 128 * KP;   // NT*K
    const int tid = threadIdx.x;
    const int jbase = blockIdx.y * JPT * 128;

    for (int idx = tid; idx < JPT * 128 * K; idx += 128) {
        int r = idx / K, k = idx - r * K;
        Ws[r * KP + k] = W[(size_t)(jbase + r) * wstride + k];
    }
    float b[JPT];
#pragma unroll
    for (int c = 0; c < JPT; ++c)
        b[c] = bias ? bias[jbase + tid + c * 128] : 0.0f;

    const int stride = gridDim.x * NT;
    int t0 = blockIdx.x * NT;
    float4 pre[NPRE];
    if (t0 < n) {
        int lim = min(NT, n - t0) * (K / 4);
#pragma unroll
        for (int i = 0; i < NPRE; ++i) {
            int idx = tid + i * 128;
            pre[i] = (idx < lim) ? ((const float4*)(A + (size_t)t0 * K))[idx]
                                 : make_float4(0.f, 0.f, 0.f, 0.f);
        }
    }
    __syncthreads();

    for (; t0 < n; t0 += stride) {
        int cnt = min(NT, n - t0);
#pragma unroll
        for (int i = 0; i < NPRE; ++i)
            ((float4*)ins)[tid + i * 128] = pre[i];
        __syncthreads();
        int tn = t0 + stride;
        if (tn < n) {
            int lim = min(NT, n - tn) * (K / 4);
#pragma unroll
            for (int i = 0; i < NPRE; ++i) {
                int idx = tid + i * 128;
                pre[i] = (idx < lim) ? ((const float4*)(A + (size_t)tn * K))[idx]
                                     : make_float4(0.f, 0.f, 0.f, 0.f);
            }
        }
        float acc[JPT][NT];
#pragma unroll
        for (int c = 0; c < JPT; ++c)
#pragma unroll
            for (int q = 0; q < NT; ++q) acc[c][q] = 0.f;

        const float4* ins4 = (const float4*)ins;
#pragma unroll 2
        for (int k4 = 0; k4 < K / 4; ++k4) {
            float4 w[JPT];
#pragma unroll
            for (int c = 0; c < JPT; ++c)
                w[c] = ((const float4*)(Ws + (size_t)(c * 128 + tid) * KP))[k4];
#pragma unroll
            for (int q = 0; q < NT; ++q) {
                float4 v = ins4[q * (K / 4) + k4];
#pragma unroll
                for (int c = 0; c < JPT; ++c) {
                    acc[c][q] += w[c].x * v.x;
                    acc[c][q] += w[c].y * v.y;
                    acc[c][q] += w[c].z * v.z;
                    acc[c][q] += w[c].w * v.w;
                }
            }
        }
        if (EPI == 0) {
            for (int q = 0; q < cnt; ++q) {
#pragma unroll
                for (int c = 0; c < JPT; ++c) {
                    float r = acc[c][q] + b[c];
                    if (ACT == 1) r = (r >= 0.f) ? r : 0.01f * r;
                    else if (ACT == 2) r = fmaxf(r, 0.f);
                    else if (ACT == 3) r = (r > 0.f) ? r : expm1f(r);
                    out[(size_t)(t0 + q) * Jtotal + jbase + tid + c * 128] = r;
                }
            }
        } else {
            for (int q = 0; q < cnt; ++q) {
                size_t node = t0 + q;
                float hr = acc[0][q] + b[0];
                float hz = acc[1][q] + b[1];
                float hn = acc[2][q] + b[2];
                size_t gbase = node * 384 + tid;
                float r = sigm(gi[gbase] + hr);
                float z = sigm(gi[gbase + 128] + hz);
                float nng = tanhf(gi[gbase + 256] + r * hn);
                float hv = ins[q * K + tid];
                out[node * 128 + tid] = fmaxf((1.f - z) * nng + z * hv, 0.f);
            }
        }
        __syncthreads();
    }
}

// ---------------- nd gather (CSR): tsum[n] = sum_e leaky(p[src]+ea@W1b^T) ---
__global__ void __launch_bounds__(256) nd_gather_kernel(
    const float* __restrict__ p, const float* __restrict__ ea,
    const int* __restrict__ src, const int* __restrict__ off,
    const int* __restrict__ eid, const float* __restrict__ w1,
    float* __restrict__ tsum)
{
    __shared__ float W1b[16 * 128];   // [k][j]
    const int tid = threadIdx.x;
    for (int idx = tid; idx < 16 * 128; idx += 256) {
        int k = idx >> 7, j = idx & 127;
        W1b[idx] = w1[j * 144 + 128 + k];
    }
    __syncthreads();
    int n = blockIdx.x * 8 + (tid >> 5);
    if (n >= NN) return;
    int lane = tid & 31;
    int beg = off[n], end = off[n + 1];
    float4 acc = make_float4(0.f, 0.f, 0.f, 0.f);
    const float4* W1b4 = (const float4*)W1b;
    const float4* p4 = (const float4*)p;
    for (int e = beg; e < end; ++e) {
        int ed = eid[e];
        int s = src[ed];
        float eav = (lane < 16) ? __ldg(&ea[(size_t)ed * 16 + lane]) : 0.f;
        float4 t = p4[(size_t)s * 32 + lane];
#pragma unroll
        for (int k = 0; k < 16; ++k) {
            float ek = __shfl_sync(0xFFFFFFFFu, eav, k);
            float4 w = W1b4[k * 32 + lane];
            t.x += ek * w.x; t.y += ek * w.y; t.z += ek * w.z; t.w += ek * w.w;
        }
        t.x = (t.x >= 0.f) ? t.x : 0.01f * t.x;
        t.y = (t.y >= 0.f) ? t.y : 0.01f * t.y;
        t.z = (t.z >= 0.f) ? t.z : 0.01f * t.z;
        t.w = (t.w >= 0.f) ? t.w : 0.01f * t.w;
        acc.x += t.x; acc.y += t.y; acc.z += t.z; acc.w += t.w;
    }
    ((float4*)tsum)[(size_t)n * 32 + lane] = acc;
}

// ---------------- GAT attention dots ----------------
__global__ void attn_dots_kernel(const float* __restrict__ xp, const float* __restrict__ asrc,
                                 const float* __restrict__ adst, float* __restrict__ as_,
                                 float* __restrict__ ad_) {
    int n = (blockIdx.x * blockDim.x + threadIdx.x) >> 5;
    int lane = threadIdx.x & 31;
    if (n >= NN) return;
    float4 v = ((const float4*)xp)[(size_t)n * 32 + lane];
    float4 w1 = ((const float4*)asrc)[lane];
    float4 w2 = ((const float4*)adst)[lane];
    float sa = v.x * w1.x + v.y * w1.y + v.z * w1.z + v.w * w1.w;
    float sd = v.x * w2.x + v.y * w2.y + v.z * w2.z + v.w * w2.w;
#pragma unroll
    for (int o = 16; o; o >>= 1) {
        sa += __shfl_xor_sync(0xFFFFFFFFu, sa, o);
        sd += __shfl_xor_sync(0xFFFFFFFFu, sd, o);
    }
    if (lane == 0) { as_[n] = sa; ad_[n] = sd; }
}

// ---------------- GAT gather (CSR, online softmax, fused bias+elu) ----------
__global__ void __launch_bounds__(256) gat_gather_kernel(
    const int* __restrict__ src, const int* __restrict__ off, const int* __restrict__ eid,
    const float* __restrict__ as_, const float* __restrict__ ad_,
    const float* __restrict__ xp, const float* __restrict__ bias,
    float* __restrict__ hout)
{
    int n = blockIdx.x * 8 + (threadIdx.x >> 5);
    if (n >= NN) return;
    int lane = threadIdx.x & 31;
    int beg = off[n], end = off[n + 1];
    float adn = ad_[n];
    float m = -INFINITY, den = 0.f;
    float4 acc = make_float4(0.f, 0.f, 0.f, 0.f);
    const float4* xp4 = (const float4*)xp;
    for (int e = beg; e < end; ++e) {
        int ed = eid[e];
        int s = src[ed];
        float a = __ldg(&as_[s]) + adn;
        a = (a >= 0.f) ? a : 0.01f * a;
        if (a > m) {
            float f = __expf(m - a);   // exp(-inf)=0 on first edge
            den *= f;
            acc.x *= f; acc.y *= f; acc.z *= f; acc.w *= f;
            m = a;
        }
        float w = __expf(a - m);
        den += w;
        float4 v = xp4[(size_t)s * 32 + lane];
        acc.x += w * v.x; acc.y += w * v.y; acc.z += w * v.z; acc.w += w * v.w;
    }
    float inv = (den > 0.f) ? 1.f / den : 0.f;
    float4 b = ((const float4*)bias)[lane];
    float4 r;
    r.x = acc.x * inv + b.x; r.y = acc.y * inv + b.y;
    r.z = acc.z * inv + b.z; r.w = acc.w * inv + b.w;
    r.x = (r.x > 0.f) ? r.x : expm1f(r.x);
    r.y = (r.y > 0.f) ? r.y : expm1f(r.y);
    r.z = (r.z > 0.f) ? r.z : expm1f(r.z);
    r.w = (r.w > 0.f) ? r.w : expm1f(r.w);
    ((float4*)hout)[(size_t)n * 32 + lane] = r;
}

// ---------------- readout ----------------
__global__ void __launch_bounds__(128) graph_agg_kernel(const float* __restrict__ xcur,
                                                        const int* __restrict__ batch,
                                                        float* __restrict__ agg,
                                                        float* __restrict__ outv) {
    int g = blockIdx.x;
    int lo, hi;
    {
        int l = 0, r = NN;
        while (l < r) { int m = (l + r) >> 1; if (batch[m] < g) l = m + 1; else r = m; }
        lo = l;
    }
    {
        int l = lo, r = NN;
        while (l < r) { int m = (l + r) >> 1; if (batch[m] < g + 1) l = m + 1; else r = m; }
        hi = l;
    }
    float s = 0.f;
    for (int n = lo; n < hi; ++n) s += xcur[(size_t)n * 128 + threadIdx.x];
    agg[g * 128 + threadIdx.x] = s;
    outv[g * 128 + threadIdx.x] = fmaxf(s, 0.f);
}

__global__ void add_kernel(const float* __restrict__ a, const float* __restrict__ b,
                           float* __restrict__ c, int n) {
    int t = blockIdx.x * blockDim.x + threadIdx.x;
    if (t < n) c[t] = a[t] + b[t];
}

__global__ void lstm_combine_kernel(const float* __restrict__ gi, const float* __restrict__ gh,
                                    const float* __restrict__ hc, float* __restrict__ out) {
    int t = blockIdx.x * blockDim.x + threadIdx.x;
    if (t >= NG * 128) return;
    int g = t >> 7, j = t & 127;
    size_t base = (size_t)g * 512;
    float gI = gi[base + j]       + gh[base + j];
    float gF = gi[base + 128 + j] + gh[base + 128 + j];
    float gG = gi[base + 256 + j] + gh[base + 256 + j];
    float gO = gi[base + 384 + j] + gh[base + 384 + j];
    float c = hc[t];
    float c2 = sigm(gF) * c + sigm(gI) * tanhf(gG);
    out[t] = sigm(gO) * tanhf(c2);
}

__global__ void final_kernel(const float* __restrict__ outv, const float* __restrict__ w,
                             const float* __restrict__ b, float* __restrict__ res) {
    int g = (blockIdx.x * blockDim.x + threadIdx.x) >> 5;
    int lane = threadIdx.x & 31;
    if (g >= NG) return;
    float4 v = ((const float4*)outv)[(size_t)g * 32 + lane];
    float4 ww = ((const float4*)w)[lane];
    float s = v.x * ww.x + v.y * ww.y + v.z * ww.z + v.w * ww.w;
#pragma unroll
    for (int o = 16; o; o >>= 1) s += __shfl_xor_sync(0xFFFFFFFFu, s, o);
    if (lane == 0) res[g] = s + b[0];
}

// ---------------- host ----------------
#define SM_J1K64  ((128 * 68 + 16 * 64) * 4)
#define SM_J1K128 ((128 * 132 + 16 * 128) * 4)
#define SM_J3K128 ((384 * 132 + 16 * 128) * 4)

extern "C" void kernel_launch(void* const* d_in, const int* in_sizes, int n_in,
                              void* d_out, int out_size) {
    const float* x        = (const float*)d_in[0];
    const int*   ei       = (const int*)  d_in[1];
    const float* ea       = (const float*)d_in[2];
    const int*   batch    = (const int*)  d_in[3];
    const float* lin1_w   = (const float*)d_in[4];
    const float* lin1_b   = (const float*)d_in[5];
    const float* nd_lin1w = (const float*)d_in[6];
    const float* nd_lin2w = (const float*)d_in[7];
    const float* nd_bias  = (const float*)d_in[8];
    const float* gru0_wih = (const float*)d_in[9];
    const float* gru0_whh = (const float*)d_in[10];
    const float* gru0_bih = (const float*)d_in[11];
    const float* gru0_bhh = (const float*)d_in[12];
    const float* gat_w    = (const float*)d_in[13];
    const float* gat_asrc = (const float*)d_in[14];
    const float* gat_adst = (const float*)d_in[15];
    const float* gat_b    = (const float*)d_in[16];
    const float* gru_wih  = (const float*)d_in[17];
    const float* gru_whh  = (const float*)d_in[18];
    const float* gru_bih  = (const float*)d_in[19];
    const float* gru_bhh  = (const float*)d_in[20];
    const float* gin_w    = (const float*)d_in[21];
    const float* gin_b    = (const float*)d_in[22];
    const float* lstm_wih = (const float*)d_in[23];
    const float* lstm_whh = (const float*)d_in[24];
    const float* lstm_bih = (const float*)d_in[25];
    const float* lstm_bhh = (const float*)d_in[26];
    const float* lin2_w   = (const float*)d_in[27];
    const float* lin2_b   = (const float*)d_in[28];
    float* out = (float*)d_out;

    const int* src = ei;
    const int* dst = ei + NE;

    float *px1, *pp, *ph, *pxc, *pgi, *pas, *pad;
    float *pagg, *pgout, *pghh, *pgtmp, *pggi, *pggh;
    int *pcnt, *poff, *ppos, *peid;
    cudaGetSymbolAddress((void**)&px1, f_x1);
    cudaGetSymbolAddress((void**)&pp, f_p);
    cudaGetSymbolAddress((void**)&ph, f_h);
    cudaGetSymbolAddress((void**)&pxc, f_xcur);
    cudaGetSymbolAddress((void**)&pgi, f_gi);
    cudaGetSymbolAddress((void**)&pas, f_as);
    cudaGetSymbolAddress((void**)&pad, f_ad);
    cudaGetSymbolAddress((void**)&pagg, g_agg);
    cudaGetSymbolAddress((void**)&pgout, g_out);
    cudaGetSymbolAddress((void**)&pghh, g_hh);
    cudaGetSymbolAddress((void**)&pgtmp, g_tmp);
    cudaGetSymbolAddress((void**)&pggi, g_gi);
    cudaGetSymbolAddress((void**)&pggh, g_gh);
    cudaGetSymbolAddress((void**)&pcnt, c_cnt);
    cudaGetSymbolAddress((void**)&poff, c_off);
    cudaGetSymbolAddress((void**)&ppos, c_pos);
    cudaGetSymbolAddress((void**)&peid, c_eid);

    cudaFuncSetAttribute((const void*)dense_kernel<64, 1, 1, 0>, cudaFuncAttributeMaxDynamicSharedMemorySize, SM_J1K64);
    cudaFuncSetAttribute((const void*)dense_kernel<128, 1, 0, 0>, cudaFuncAttributeMaxDynamicSharedMemorySize, SM_J1K128);
    cudaFuncSetAttribute((const void*)dense_kernel<128, 1, 3, 0>, cudaFuncAttributeMaxDynamicSharedMemorySize, SM_J1K128);
    cudaFuncSetAttribute((const void*)dense_kernel<128, 3, 0, 0>, cudaFuncAttributeMaxDynamicSharedMemorySize, SM_J3K128);
    cudaFuncSetAttribute((const void*)dense_kernel<128, 3, 0, 1>, cudaFuncAttributeMaxDynamicSharedMemorySize, SM_J3K128);

    const int tilesN = (NN + 15) / 16;   // 3125
    const int tilesG = (NG + 15) / 16;   // 125
    const int ZB = 256;

    // ---- CSR build (by dst) ----
    zero_i_kernel<<<(NN + ZB - 1) / ZB, ZB>>>(pcnt, NN);
    hist_kernel<<<(NE + ZB - 1) / ZB, ZB>>>(dst, pcnt);
    scan_kernel<<<1, 1024>>>(pcnt, poff, ppos);
    fill_kernel<<<(NE + ZB - 1) / ZB, ZB>>>(dst, ppos, peid);

    // ---- x1 = leaky(x @ lin1_w.T + b) ----
    dense_kernel<64, 1, 1, 0><<<dim3(tilesN, 1), 128, SM_J1K64>>>(x, lin1_w, lin1_b, px1, nullptr, NN, 128, 64);
    // ---- p = x1 @ W1a.T ----
    dense_kernel<128, 1, 0, 0><<<dim3(tilesN, 1), 128, SM_J1K128>>>(px1, nd_lin1w, nullptr, pp, nullptr, NN, 128, 144);
    // ---- tsum = segment_sum(leaky(p[src] + ea @ W1b.T)) ----
    nd_gather_kernel<<<(NN + 7) / 8, 256>>>(pp, ea, src, poff, peid, nd_lin1w, pgi);
    // ---- h = elu(tsum @ W2.T + nd_bias) ----
    dense_kernel<128, 1, 3, 0><<<dim3(tilesN, 1), 128, SM_J1K128>>>(pgi, nd_lin2w, nd_bias, ph, nullptr, NN, 128, 128);
    // ---- GRU0: xcur = relu(gru(h, x1)) ----
    dense_kernel<128, 3, 0, 0><<<dim3(tilesN, 1), 128, SM_J3K128>>>(ph, gru0_wih, gru0_bih, pgi, nullptr, NN, 384, 128);
    dense_kernel<128, 3, 0, 1><<<dim3(tilesN, 1), 128, SM_J3K128>>>(px1, gru0_whh, gru0_bhh, pxc, pgi, NN, 384, 128);

    // ---- GAT layers ----
    for (int l = 0; l < 2; ++l) {
        dense_kernel<128, 1, 0, 0><<<dim3(tilesN, 1), 128, SM_J1K128>>>(pxc, gat_w + (size_t)l * 128 * 128, nullptr, pp, nullptr, NN, 128, 128);
        attn_dots_kernel<<<(NN * 32 + ZB - 1) / ZB, ZB>>>(pp, gat_asrc + l * 128, gat_adst + l * 128, pas, pad);
        gat_gather_kernel<<<(NN + 7) / 8, 256>>>(src, poff, peid, pas, pad, pp, gat_b + l * 128, ph);
        dense_kernel<128, 3, 0, 0><<<dim3(tilesN, 1), 128, SM_J3K128>>>(ph, gru_wih + (size_t)l * 384 * 128, gru_bih + l * 384, pgi, nullptr, NN, 384, 128);
        dense_kernel<128, 3, 0, 1><<<dim3(tilesN, 1), 128, SM_J3K128>>>(pxc, gru_whh + (size_t)l * 384 * 128, gru_bhh + l * 384, pxc, pgi, NN, 384, 128);
    }

    // ---- readout ----
    graph_agg_kernel<<<NG, 128>>>(pxc, batch, pagg, pgout);
    for (int t = 0; t < 2; ++t) {
        add_kernel<<<(NG * 128 + ZB - 1) / ZB, ZB>>>(pgout, pagg, pgtmp, NG * 128);
        dense_kernel<128, 1, 3, 0><<<dim3(tilesG, 1), 128, SM_J1K128>>>(pgtmp, gin_w, gin_b, pghh, nullptr, NG, 128, 128);
        dense_kernel<128, 1, 0, 0><<<dim3(tilesG, 4), 128, SM_J1K128>>>(pgout, lstm_wih, lstm_bih, pggi, nullptr, NG, 512, 128);
        dense_kernel<128, 1, 0, 0><<<dim3(tilesG, 4), 128, SM_J1K128>>>(pghh, lstm_whh, lstm_bhh, pggh, nullptr, NG, 512, 128);
        lstm_combine_kernel<<<(NG * 128 + ZB - 1) / ZB, ZB>>>(pggi, pggh, pghh, pgout);
    }
    final_kernel<<<(NG * 32 + 127) / 128, 128>>>(pgout, lin2_w, lin2_b, out);
}

// round 3
// speedup vs baseline: 1.6722x; 1.6722x over previous
#include <cuda_runtime.h>
#include <math.h>

#define NN 50000
#define NE 500000
#define NG 2000

// ---------------- scratch (device globals) ----------------
__device__ float f_x1  [NN * 128];
__device__ float f_p   [NN * 128];      // p / xp
__device__ float f_h   [NN * 128];
__device__ float f_xcur[NN * 128];
__device__ float f_gi  [NN * 3 * 128];  // also reused as tsum (first NN*128)
__device__ float f_as  [NN];
__device__ float f_ad  [NN];
__device__ float g_agg [NG * 128];
__device__ float g_out [NG * 128];
__device__ float g_hh  [NG * 128];
__device__ float g_tmp [NG * 128];
__device__ float g_gi  [NG * 4 * 128];
__device__ float g_gh  [NG * 4 * 128];
// CSR
__device__ int c_cnt[NN];
__device__ int c_off[NN + 1];
__device__ int c_pos[NN];
__device__ int c_eid[NE];

__device__ __forceinline__ float sigm(float x) { return 1.0f / (1.0f + expf(-x)); }

// ---------------- CSR build ----------------
__global__ void zero_i_kernel(int* p, int n) {
    int t = blockIdx.x * blockDim.x + threadIdx.x;
    if (t < n) p[t] = 0;
}
__global__ void hist_kernel(const int* __restrict__ dst, int* __restrict__ cnt) {
    int e = blockIdx.x * blockDim.x + threadIdx.x;
    if (e < NE) atomicAdd(&cnt[dst[e]], 1);
}
__global__ void __launch_bounds__(1024) scan_kernel(const int* __restrict__ cnt,
                                                    int* __restrict__ off, int* __restrict__ pos) {
    __shared__ int sm[1024];
    __shared__ int s_carry;
    const int tid = threadIdx.x;
    if (tid == 0) s_carry = 0;
    __syncthreads();
    const int CH = 1024 * 8;
    for (int base = 0; base < NN; base += CH) {
        int v[8]; int s = 0;
        int i0 = base + tid * 8;
#pragma unroll
        for (int j = 0; j < 8; ++j) {
            int i = i0 + j;
            v[j] = (i < NN) ? cnt[i] : 0;
            s += v[j];
        }
        sm[tid] = s;
        __syncthreads();
        for (int d = 1; d < 1024; d <<= 1) {
            int t = (tid >= d) ? sm[tid - d] : 0;
            __syncthreads();
            sm[tid] += t;
            __syncthreads();
        }
        int pref = sm[tid] - s + s_carry;
        int total = sm[1023];
#pragma unroll
        for (int j = 0; j < 8; ++j) {
            int i = i0 + j;
            if (i < NN) { off[i] = pref; pos[i] = pref; }
            pref += v[j];
        }
        __syncthreads();
        if (tid == 0) s_carry += total;
        __syncthreads();
    }
    if (tid == 0) off[NN] = NE;
}
__global__ void fill_kernel(const int* __restrict__ dst, int* __restrict__ pos,
                            int* __restrict__ eid) {
    int e = blockIdx.x * blockDim.x + threadIdx.x;
    if (e < NE) {
        int idx = atomicAdd(&pos[dst[e]], 1);
        eid[idx] = e;
    }
}

// ---------------- dense GEMM (persistent blocks; weights amortized) -------
// out[n, jbase + tid + c*128] = act(sum_k A[n,k]*W[j*wstride+k] + b)
// EPI==1 (JPT==3): fused GRU combine; gi precomputed, hprev = A row.
template <int K, int JPT, int ACT, int EPI>
__global__ void __launch_bounds__(128) dense_kernel(
    const float* __restrict__ A, const float* __restrict__ W,
    const float* __restrict__ bias, float* __restrict__ out,
    const float* __restrict__ gi, int n, int Jtotal, int wstride)
{
    constexpr int KP = K + 4;
    constexpr int NT = 16;
    constexpr int NPRE = NT * K / 512;
    extern __shared__ float sm[];
    float* Ws = sm;                     // JPT*128*KP
    float* ins = sm + JPT * 128 * KP;   // NT*K
    const int tid = threadIdx.x;
    const int jbase = blockIdx.y * JPT * 128;

    for (int idx = tid; idx < JPT * 128 * K; idx += 128) {
        int r = idx / K, k = idx - r * K;
        Ws[r * KP + k] = W[(size_t)(jbase + r) * wstride + k];
    }
    float b[JPT];
#pragma unroll
    for (int c = 0; c < JPT; ++c)
        b[c] = bias ? bias[jbase + tid + c * 128] : 0.0f;

    const int stride = gridDim.x * NT;
    int t0 = blockIdx.x * NT;
    float4 pre[NPRE];
    if (t0 < n) {
        int lim = min(NT, n - t0) * (K / 4);
#pragma unroll
        for (int i = 0; i < NPRE; ++i) {
            int idx = tid + i * 128;
            pre[i] = (idx < lim) ? ((const float4*)(A + (size_t)t0 * K))[idx]
                                 : make_float4(0.f, 0.f, 0.f, 0.f);
        }
    }
    __syncthreads();

    for (; t0 < n; t0 += stride) {
        int cnt = min(NT, n - t0);
#pragma unroll
        for (int i = 0; i < NPRE; ++i)
            ((float4*)ins)[tid + i * 128] = pre[i];
        __syncthreads();
        int tn = t0 + stride;
        if (tn < n) {
            int lim = min(NT, n - tn) * (K / 4);
#pragma unroll
            for (int i = 0; i < NPRE; ++i) {
                int idx = tid + i * 128;
                pre[i] = (idx < lim) ? ((const float4*)(A + (size_t)tn * K))[idx]
                                     : make_float4(0.f, 0.f, 0.f, 0.f);
            }
        }
        float acc[JPT][NT];
#pragma unroll
        for (int c = 0; c < JPT; ++c)
#pragma unroll
            for (int q = 0; q < NT; ++q) acc[c][q] = 0.f;

        const float4* ins4 = (const float4*)ins;
#pragma unroll 2
        for (int k4 = 0; k4 < K / 4; ++k4) {
            float4 w[JPT];
#pragma unroll
            for (int c = 0; c < JPT; ++c)
                w[c] = ((const float4*)(Ws + (size_t)(c * 128 + tid) * KP))[k4];
#pragma unroll
            for (int q = 0; q < NT; ++q) {
                float4 v = ins4[q * (K / 4) + k4];
#pragma unroll
                for (int c = 0; c < JPT; ++c) {
                    acc[c][q] += w[c].x * v.x;
                    acc[c][q] += w[c].y * v.y;
                    acc[c][q] += w[c].z * v.z;
                    acc[c][q] += w[c].w * v.w;
                }
            }
        }
        if (EPI == 0) {
            for (int q = 0; q < cnt; ++q) {
#pragma unroll
                for (int c = 0; c < JPT; ++c) {
                    float r = acc[c][q] + b[c];
                    if (ACT == 1) r = (r >= 0.f) ? r : 0.01f * r;
                    else if (ACT == 2) r = fmaxf(r, 0.f);
                    else if (ACT == 3) r = (r > 0.f) ? r : expm1f(r);
                    out[(size_t)(t0 + q) * Jtotal + jbase + tid + c * 128] = r;
                }
            }
        } else {
            for (int q = 0; q < cnt; ++q) {
                size_t node = t0 + q;
                float hr = acc[0][q] + b[0];
                float hz = acc[1][q] + b[1];
                float hn = acc[2][q] + b[2];
                size_t gbase = node * 384 + tid;
                float r = sigm(gi[gbase] + hr);
                float z = sigm(gi[gbase + 128] + hz);
                float nng = tanhf(gi[gbase + 256] + r * hn);
                float hv = ins[q * K + tid];
                out[node * 128 + tid] = fmaxf((1.f - z) * nng + z * hv, 0.f);
            }
        }
        __syncthreads();
    }
}

// ---------------- nd gather (CSR): tsum[n] = sum_e leaky(p[src]+ea@W1b^T) ---
__global__ void __launch_bounds__(256) nd_gather_kernel(
    const float* __restrict__ p, const float* __restrict__ ea,
    const int* __restrict__ src, const int* __restrict__ off,
    const int* __restrict__ eid, const float* __restrict__ w1,
    float* __restrict__ tsum)
{
    __shared__ float W1b[16 * 128];   // [k][j]
    const int tid = threadIdx.x;
    for (int idx = tid; idx < 16 * 128; idx += 256) {
        int k = idx >> 7, j = idx & 127;
        W1b[idx] = w1[j * 144 + 128 + k];
    }
    __syncthreads();
    int n = blockIdx.x * 8 + (tid >> 5);
    if (n >= NN) return;
    int lane = tid & 31;
    int beg = off[n], end = off[n + 1];
    float4 acc = make_float4(0.f, 0.f, 0.f, 0.f);
    const float4* W1b4 = (const float4*)W1b;
    const float4* p4 = (const float4*)p;
    for (int e = beg; e < end; ++e) {
        int ed = eid[e];
        int s = src[ed];
        float eav = (lane < 16) ? __ldg(&ea[(size_t)ed * 16 + lane]) : 0.f;
        float4 t = p4[(size_t)s * 32 + lane];
#pragma unroll
        for (int k = 0; k < 16; ++k) {
            float ek = __shfl_sync(0xFFFFFFFFu, eav, k);
            float4 w = W1b4[k * 32 + lane];
            t.x += ek * w.x; t.y += ek * w.y; t.z += ek * w.z; t.w += ek * w.w;
        }
        t.x = (t.x >= 0.f) ? t.x : 0.01f * t.x;
        t.y = (t.y >= 0.f) ? t.y : 0.01f * t.y;
        t.z = (t.z >= 0.f) ? t.z : 0.01f * t.z;
        t.w = (t.w >= 0.f) ? t.w : 0.01f * t.w;
        acc.x += t.x; acc.y += t.y; acc.z += t.z; acc.w += t.w;
    }
    ((float4*)tsum)[(size_t)n * 32 + lane] = acc;
}

// ---------------- GAT attention dots ----------------
__global__ void attn_dots_kernel(const float* __restrict__ xp, const float* __restrict__ asrc,
                                 const float* __restrict__ adst, float* __restrict__ as_,
                                 float* __restrict__ ad_) {
    int n = (blockIdx.x * blockDim.x + threadIdx.x) >> 5;
    int lane = threadIdx.x & 31;
    if (n >= NN) return;
    float4 v = ((const float4*)xp)[(size_t)n * 32 + lane];
    float4 w1 = ((const float4*)asrc)[lane];
    float4 w2 = ((const float4*)adst)[lane];
    float sa = v.x * w1.x + v.y * w1.y + v.z * w1.z + v.w * w1.w;
    float sd = v.x * w2.x + v.y * w2.y + v.z * w2.z + v.w * w2.w;
#pragma unroll
    for (int o = 16; o; o >>= 1) {
        sa += __shfl_xor_sync(0xFFFFFFFFu, sa, o);
        sd += __shfl_xor_sync(0xFFFFFFFFu, sd, o);
    }
    if (lane == 0) { as_[n] = sa; ad_[n] = sd; }
}

// ---------------- GAT gather (CSR, online softmax, fused bias+elu) ----------
__global__ void __launch_bounds__(256) gat_gather_kernel(
    const int* __restrict__ src, const int* __restrict__ off, const int* __restrict__ eid,
    const float* __restrict__ as_, const float* __restrict__ ad_,
    const float* __restrict__ xp, const float* __restrict__ bias,
    float* __restrict__ hout)
{
    int n = blockIdx.x * 8 + (threadIdx.x >> 5);
    if (n >= NN) return;
    int lane = threadIdx.x & 31;
    int beg = off[n], end = off[n + 1];
    float adn = ad_[n];
    float m = -INFINITY, den = 0.f;
    float4 acc = make_float4(0.f, 0.f, 0.f, 0.f);
    const float4* xp4 = (const float4*)xp;
    for (int e = beg; e < end; ++e) {
        int ed = eid[e];
        int s = src[ed];
        float a = __ldg(&as_[s]) + adn;
        a = (a >= 0.f) ? a : 0.01f * a;
        if (a > m) {
            float f = __expf(m - a);   // exp(-inf)=0 on first edge
            den *= f;
            acc.x *= f; acc.y *= f; acc.z *= f; acc.w *= f;
            m = a;
        }
        float w = __expf(a - m);
        den += w;
        float4 v = xp4[(size_t)s * 32 + lane];
        acc.x += w * v.x; acc.y += w * v.y; acc.z += w * v.z; acc.w += w * v.w;
    }
    float inv = (den > 0.f) ? 1.f / den : 0.f;
    float4 b = ((const float4*)bias)[lane];
    float4 r;
    r.x = acc.x * inv + b.x; r.y = acc.y * inv + b.y;
    r.z = acc.z * inv + b.z; r.w = acc.w * inv + b.w;
    r.x = (r.x > 0.f) ? r.x : expm1f(r.x);
    r.y = (r.y > 0.f) ? r.y : expm1f(r.y);
    r.z = (r.z > 0.f) ? r.z : expm1f(r.z);
    r.w = (r.w > 0.f) ? r.w : expm1f(r.w);
    ((float4*)hout)[(size_t)n * 32 + lane] = r;
}

// ---------------- readout ----------------
__global__ void __launch_bounds__(128) graph_agg_kernel(const float* __restrict__ xcur,
                                                        const int* __restrict__ batch,
                                                        float* __restrict__ agg,
                                                        float* __restrict__ outv) {
    int g = blockIdx.x;
    int lo, hi;
    {
        int l = 0, r = NN;
        while (l < r) { int m = (l + r) >> 1; if (batch[m] < g) l = m + 1; else r = m; }
        lo = l;
    }
    {
        int l = lo, r = NN;
        while (l < r) { int m = (l + r) >> 1; if (batch[m] < g + 1) l = m + 1; else r = m; }
        hi = l;
    }
    float s = 0.f;
    for (int n = lo; n < hi; ++n) s += xcur[(size_t)n * 128 + threadIdx.x];
    agg[g * 128 + threadIdx.x] = s;
    outv[g * 128 + threadIdx.x] = fmaxf(s, 0.f);
}

__global__ void add_kernel(const float* __restrict__ a, const float* __restrict__ b,
                           float* __restrict__ c, int n) {
    int t = blockIdx.x * blockDim.x + threadIdx.x;
    if (t < n) c[t] = a[t] + b[t];
}

__global__ void lstm_combine_kernel(const float* __restrict__ gi, const float* __restrict__ gh,
                                    const float* __restrict__ hc, float* __restrict__ out) {
    int t = blockIdx.x * blockDim.x + threadIdx.x;
    if (t >= NG * 128) return;
    int g = t >> 7, j = t & 127;
    size_t base = (size_t)g * 512;
    float gI = gi[base + j]       + gh[base + j];
    float gF = gi[base + 128 + j] + gh[base + 128 + j];
    float gG = gi[base + 256 + j] + gh[base + 256 + j];
    float gO = gi[base + 384 + j] + gh[base + 384 + j];
    float c = hc[t];
    float c2 = sigm(gF) * c + sigm(gI) * tanhf(gG);
    out[t] = sigm(gO) * tanhf(c2);
}

__global__ void final_kernel(const float* __restrict__ outv, const float* __restrict__ w,
                             const float* __restrict__ b, float* __restrict__ res) {
    int g = (blockIdx.x * blockDim.x + threadIdx.x) >> 5;
    int lane = threadIdx.x & 31;
    if (g >= NG) return;
    float4 v = ((const float4*)outv)[(size_t)g * 32 + lane];
    float4 ww = ((const float4*)w)[lane];
    float s = v.x * ww.x + v.y * ww.y + v.z * ww.z + v.w * ww.w;
#pragma unroll
    for (int o = 16; o; o >>= 1) s += __shfl_xor_sync(0xFFFFFFFFu, s, o);
    if (lane == 0) res[g] = s + b[0];
}

// ---------------- host ----------------
#define SM_J1K64  ((128 * 68 + 16 * 64) * 4)
#define SM_J1K128 ((128 * 132 + 16 * 128) * 4)
#define SM_J3K128 ((384 * 132 + 16 * 128) * 4)

extern "C" void kernel_launch(void* const* d_in, const int* in_sizes, int n_in,
                              void* d_out, int out_size) {
    const float* x        = (const float*)d_in[0];
    const int*   ei       = (const int*)  d_in[1];
    const float* ea       = (const float*)d_in[2];
    const int*   batch    = (const int*)  d_in[3];
    const float* lin1_w   = (const float*)d_in[4];
    const float* lin1_b   = (const float*)d_in[5];
    const float* nd_lin1w = (const float*)d_in[6];
    const float* nd_lin2w = (const float*)d_in[7];
    const float* nd_bias  = (const float*)d_in[8];
    const float* gru0_wih = (const float*)d_in[9];
    const float* gru0_whh = (const float*)d_in[10];
    const float* gru0_bih = (const float*)d_in[11];
    const float* gru0_bhh = (const float*)d_in[12];
    const float* gat_w    = (const float*)d_in[13];
    const float* gat_asrc = (const float*)d_in[14];
    const float* gat_adst = (const float*)d_in[15];
    const float* gat_b    = (const float*)d_in[16];
    const float* gru_wih  = (const float*)d_in[17];
    const float* gru_whh  = (const float*)d_in[18];
    const float* gru_bih  = (const float*)d_in[19];
    const float* gru_bhh  = (const float*)d_in[20];
    const float* gin_w    = (const float*)d_in[21];
    const float* gin_b    = (const float*)d_in[22];
    const float* lstm_wih = (const float*)d_in[23];
    const float* lstm_whh = (const float*)d_in[24];
    const float* lstm_bih = (const float*)d_in[25];
    const float* lstm_bhh = (const float*)d_in[26];
    const float* lin2_w   = (const float*)d_in[27];
    const float* lin2_b   = (const float*)d_in[28];
    float* out = (float*)d_out;

    const int* src = ei;
    const int* dst = ei + NE;

    float *px1, *pp, *ph, *pxc, *pgi, *pas, *pad;
    float *pagg, *pgout, *pghh, *pgtmp, *pggi, *pggh;
    int *pcnt, *poff, *ppos, *peid;
    cudaGetSymbolAddress((void**)&px1, f_x1);
    cudaGetSymbolAddress((void**)&pp, f_p);
    cudaGetSymbolAddress((void**)&ph, f_h);
    cudaGetSymbolAddress((void**)&pxc, f_xcur);
    cudaGetSymbolAddress((void**)&pgi, f_gi);
    cudaGetSymbolAddress((void**)&pas, f_as);
    cudaGetSymbolAddress((void**)&pad, f_ad);
    cudaGetSymbolAddress((void**)&pagg, g_agg);
    cudaGetSymbolAddress((void**)&pgout, g_out);
    cudaGetSymbolAddress((void**)&pghh, g_hh);
    cudaGetSymbolAddress((void**)&pgtmp, g_tmp);
    cudaGetSymbolAddress((void**)&pggi, g_gi);
    cudaGetSymbolAddress((void**)&pggh, g_gh);
    cudaGetSymbolAddress((void**)&pcnt, c_cnt);
    cudaGetSymbolAddress((void**)&poff, c_off);
    cudaGetSymbolAddress((void**)&ppos, c_pos);
    cudaGetSymbolAddress((void**)&peid, c_eid);

    cudaFuncSetAttribute((const void*)dense_kernel<64, 1, 1, 0>, cudaFuncAttributeMaxDynamicSharedMemorySize, SM_J1K64);
    cudaFuncSetAttribute((const void*)dense_kernel<128, 1, 0, 0>, cudaFuncAttributeMaxDynamicSharedMemorySize, SM_J1K128);
    cudaFuncSetAttribute((const void*)dense_kernel<128, 1, 3, 0>, cudaFuncAttributeMaxDynamicSharedMemorySize, SM_J1K128);
    cudaFuncSetAttribute((const void*)dense_kernel<128, 3, 0, 0>, cudaFuncAttributeMaxDynamicSharedMemorySize, SM_J3K128);
    cudaFuncSetAttribute((const void*)dense_kernel<128, 3, 0, 1>, cudaFuncAttributeMaxDynamicSharedMemorySize, SM_J3K128);

    // persistent grids: weights loaded once per block, swept over many tiles
    const int GP1 = 444;   // JPT=1 K=128: 3 CTAs/SM (75KB smem each)
    const int GP1b = 592;  // JPT=1 K=64: ~4-5 CTAs/SM (39KB)
    const int GP3 = 148;   // JPT=3: 1 CTA/SM (211KB)
    const int tilesG = (NG + 15) / 16;   // 125 (tiny; one tile per block fine)
    const int ZB = 256;

    // ---- CSR build (by dst) ----
    zero_i_kernel<<<(NN + ZB - 1) / ZB, ZB>>>(pcnt, NN);
    hist_kernel<<<(NE + ZB - 1) / ZB, ZB>>>(dst, pcnt);
    scan_kernel<<<1, 1024>>>(pcnt, poff, ppos);
    fill_kernel<<<(NE + ZB - 1) / ZB, ZB>>>(dst, ppos, peid);

    // ---- x1 = leaky(x @ lin1_w.T + b) ----
    dense_kernel<64, 1, 1, 0><<<dim3(GP1b, 1), 128, SM_J1K64>>>(x, lin1_w, lin1_b, px1, nullptr, NN, 128, 64);
    // ---- p = x1 @ W1a.T ----
    dense_kernel<128, 1, 0, 0><<<dim3(GP1, 1), 128, SM_J1K128>>>(px1, nd_lin1w, nullptr, pp, nullptr, NN, 128, 144);
    // ---- tsum = segment_sum(leaky(p[src] + ea @ W1b.T)) ----
    nd_gather_kernel<<<(NN + 7) / 8, 256>>>(pp, ea, src, poff, peid, nd_lin1w, pgi);
    // ---- h = elu(tsum @ W2.T + nd_bias) ----
    dense_kernel<128, 1, 3, 0><<<dim3(GP1, 1), 128, SM_J1K128>>>(pgi, nd_lin2w, nd_bias, ph, nullptr, NN, 128, 128);
    // ---- GRU0: xcur = relu(gru(h, x1)) ----
    dense_kernel<128, 3, 0, 0><<<dim3(GP3, 1), 128, SM_J3K128>>>(ph, gru0_wih, gru0_bih, pgi, nullptr, NN, 384, 128);
    dense_kernel<128, 3, 0, 1><<<dim3(GP3, 1), 128, SM_J3K128>>>(px1, gru0_whh, gru0_bhh, pxc, pgi, NN, 384, 128);

    // ---- GAT layers ----
    for (int l = 0; l < 2; ++l) {
        dense_kernel<128, 1, 0, 0><<<dim3(GP1, 1), 128, SM_J1K128>>>(pxc, gat_w + (size_t)l * 128 * 128, nullptr, pp, nullptr, NN, 128, 128);
        attn_dots_kernel<<<(NN * 32 + ZB - 1) / ZB, ZB>>>(pp, gat_asrc + l * 128, gat_adst + l * 128, pas, pad);
        gat_gather_kernel<<<(NN + 7) / 8, 256>>>(src, poff, peid, pas, pad, pp, gat_b + l * 128, ph);
        dense_kernel<128, 3, 0, 0><<<dim3(GP3, 1), 128, SM_J3K128>>>(ph, gru_wih + (size_t)l * 384 * 128, gru_bih + l * 384, pgi, nullptr, NN, 384, 128);
        dense_kernel<128, 3, 0, 1><<<dim3(GP3, 1), 128, SM_J3K128>>>(pxc, gru_whh + (size_t)l * 384 * 128, gru_bhh + l * 384, pxc, pgi, NN, 384, 128);
    }

    // ---- readout ----
    graph_agg_kernel<<<NG, 128>>>(pxc, batch, pagg, pgout);
    for (int t = 0; t < 2; ++t) {
        add_kernel<<<(NG * 128 + ZB - 1) / ZB, ZB>>>(pgout, pagg, pgtmp, NG * 128);
        dense_kernel<128, 1, 3, 0><<<dim3(tilesG, 1), 128, SM_J1K128>>>(pgtmp, gin_w, gin_b, pghh, nullptr, NG, 128, 128);
        dense_kernel<128, 1, 0, 0><<<dim3(tilesG, 4), 128, SM_J1K128>>>(pgout, lstm_wih, lstm_bih, pggi, nullptr, NG, 512, 128);
        dense_kernel<128, 1, 0, 0><<<dim3(tilesG, 4), 128, SM_J1K128>>>(pghh, lstm_whh, lstm_bhh, pggh, nullptr, NG, 512, 128);
        lstm_combine_kernel<<<(NG * 128 + ZB - 1) / ZB, ZB>>>(pggi, pggh, pghh, pgout);
    }
    final_kernel<<<(NG * 32 + 127) / 128, 128>>>(pgout, lin2_w, lin2_b, out);
}